// round 1
// baseline (speedup 1.0000x reference)
#include <cuda_runtime.h>
#include <stdint.h>

#define NP   8192
#define MM   4096
#define BB   4
#define KK   64
#define CIN  64
#define FDIM 67
#define H1D  64
#define H2D  128
#define CAP  512

// exact same constant the reference compares against: f32(0.2*0.2 in double)
#define R2C ((float)(0.2 * 0.2))

// -------- scratch (device globals; no allocation allowed) --------
__device__ float g_q[BB * MM * 3];
__device__ int   g_nbr[BB * MM * KK];
__device__ int   g_nbrcnt[BB * MM];

// =====================================================================
// Kernel 1: farthest point sampling. One block per cloud.
// dists live in registers (16/thread, strided ownership => conflict-free LDS),
// positions in dynamic smem. Argmax = value-only fmax during the update pass,
// then exact-value match + atomicMin on the global index (== jnp.argmax
// first-index tie-break).
// =====================================================================
__global__ void __launch_bounds__(512) fps_kernel(const float* __restrict__ pos)
{
    extern __shared__ float sm[];
    float* sx = sm;
    float* sy = sm + NP;
    float* sz = sm + 2 * NP;
    __shared__ float rv[16];
    __shared__ float s_vmax;
    __shared__ int   s_widx;

    const int b = blockIdx.x, tid = threadIdx.x;
    const float* pb = pos + (size_t)b * NP * 3;

    for (int i = tid; i < NP; i += 512) {
        sx[i] = pb[3 * i + 0];
        sy[i] = pb[3 * i + 1];
        sz[i] = pb[3 * i + 2];
    }
    __syncthreads();

    float cx = sx[0], cy = sy[0], cz = sz[0];
    float d[16];
    float tv = -1.0f;
#pragma unroll
    for (int i = 0; i < 16; i++) {
        int g = tid + 512 * i;                 // strided ownership
        float dx = sx[g] - cx, dy = sy[g] - cy, dz = sz[g] - cz;
        d[i] = dx * dx + dy * dy + dz * dz;
        tv = fmaxf(tv, d[i]);
    }
    if (tid == 0) {
        g_q[(b * MM) * 3 + 0] = cx;
        g_q[(b * MM) * 3 + 1] = cy;
        g_q[(b * MM) * 3 + 2] = cz;
    }

    for (int t = 1; t < MM; t++) {
        // block-wide max of d
        float wv = tv;
#pragma unroll
        for (int o = 16; o > 0; o >>= 1)
            wv = fmaxf(wv, __shfl_xor_sync(0xffffffffu, wv, o));
        if ((tid & 31) == 0) rv[tid >> 5] = wv;
        __syncthreads();
        if (tid < 32) {
            float v = (tid < 16) ? rv[tid] : -1.0f;
#pragma unroll
            for (int o = 8; o > 0; o >>= 1)
                v = fmaxf(v, __shfl_xor_sync(0xffffffffu, v, o));
            if (tid == 0) { s_vmax = v; s_widx = 0x7FFFFFFF; }
        }
        __syncthreads();
        const float vm = s_vmax;
        if (tv == vm) {                    // only potential winners scan
#pragma unroll
            for (int i = 0; i < 16; i++)
                if (d[i] == vm) atomicMin(&s_widx, tid + 512 * i);
        }
        __syncthreads();
        const int w = s_widx;
        cx = sx[w]; cy = sy[w]; cz = sz[w];
        if (tid == 0) {
            g_q[(b * MM + t) * 3 + 0] = cx;
            g_q[(b * MM + t) * 3 + 1] = cy;
            g_q[(b * MM + t) * 3 + 2] = cz;
        }
        // fused min-update + local max scan
        tv = -1.0f;
#pragma unroll
        for (int i = 0; i < 16; i++) {
            int g = tid + 512 * i;
            float dx = sx[g] - cx, dy = sy[g] - cy, dz = sz[g] - cz;
            float nd = dx * dx + dy * dy + dz * dz;
            d[i] = fminf(d[i], nd);
            tv = fmaxf(tv, d[i]);
        }
    }
}

// =====================================================================
// Kernel 2: radius + K-nearest via candidate compaction + bitonic sort on
// (d2_bits<<32 | idx) keys. 4 centroids per block (pos traffic /4).
// Also writes pos_out and batch_out sections of d_out.
// =====================================================================
__global__ void __launch_bounds__(256) nbr_kernel(const float* __restrict__ pos,
                                                  float* __restrict__ out, int out_size)
{
    __shared__ unsigned long long keys[4][CAP];
    __shared__ int scnt[4];
    __shared__ float qx[4], qy[4], qz[4];

    const int tid = threadIdx.x;
    const int cbase = blockIdx.x * 4;      // 4 centroids, same cloud (4 | MM)
    const int b = cbase / MM;

    if (tid < 4) {
        scnt[tid] = 0;
        qx[tid] = g_q[(cbase + tid) * 3 + 0];
        qy[tid] = g_q[(cbase + tid) * 3 + 1];
        qz[tid] = g_q[(cbase + tid) * 3 + 2];
    }
    __syncthreads();

    const float q0x = qx[0], q0y = qy[0], q0z = qz[0];
    const float q1x = qx[1], q1y = qy[1], q1z = qz[1];
    const float q2x = qx[2], q2y = qy[2], q2z = qz[2];
    const float q3x = qx[3], q3y = qy[3], q3z = qz[3];

    const float* pb = pos + (size_t)b * NP * 3;
    for (int i = tid; i < NP; i += 256) {
        float px = pb[3 * i + 0], py = pb[3 * i + 1], pz = pb[3 * i + 2];
        {
            float dx = q0x - px, dy = q0y - py, dz = q0z - pz;
            float d2 = dx * dx + dy * dy + dz * dz;
            if (d2 <= R2C) { int p = atomicAdd(&scnt[0], 1);
                if (p < CAP) keys[0][p] = ((unsigned long long)__float_as_uint(d2) << 32) | (unsigned)i; }
        }
        {
            float dx = q1x - px, dy = q1y - py, dz = q1z - pz;
            float d2 = dx * dx + dy * dy + dz * dz;
            if (d2 <= R2C) { int p = atomicAdd(&scnt[1], 1);
                if (p < CAP) keys[1][p] = ((unsigned long long)__float_as_uint(d2) << 32) | (unsigned)i; }
        }
        {
            float dx = q2x - px, dy = q2y - py, dz = q2z - pz;
            float d2 = dx * dx + dy * dy + dz * dz;
            if (d2 <= R2C) { int p = atomicAdd(&scnt[2], 1);
                if (p < CAP) keys[2][p] = ((unsigned long long)__float_as_uint(d2) << 32) | (unsigned)i; }
        }
        {
            float dx = q3x - px, dy = q3y - py, dz = q3z - pz;
            float d2 = dx * dx + dy * dy + dz * dz;
            if (d2 <= R2C) { int p = atomicAdd(&scnt[3], 1);
                if (p < CAP) keys[3][p] = ((unsigned long long)__float_as_uint(d2) << 32) | (unsigned)i; }
        }
    }
    __syncthreads();

    const int grp = tid >> 6, lane = tid & 63;
    const int n = min(scnt[grp], CAP);
    for (int i = lane; i < CAP; i += 64)
        if (i >= n) keys[grp][i] = 0xFFFFFFFFFFFFFFFFull;
    __syncthreads();

    // bitonic sort ascending — 4 groups in lockstep, one bar serves all
    for (int k = 2; k <= CAP; k <<= 1) {
        for (int j = k >> 1; j > 0; j >>= 1) {
            for (int i = lane; i < CAP; i += 64) {
                int ixj = i ^ j;
                if (ixj > i) {
                    unsigned long long a = keys[grp][i];
                    unsigned long long c = keys[grp][ixj];
                    bool up = ((i & k) == 0);
                    if ((a > c) == up) { keys[grp][i] = c; keys[grp][ixj] = a; }
                }
            }
            __syncthreads();
        }
    }

    const int m = min(n, KK);
    const int cent = cbase + grp;
    if (lane < KK)
        g_nbr[cent * KK + lane] = (lane < m) ? (int)(keys[grp][lane] & 0xFFFFFFFFu) : -1;
    if (lane == 0) g_nbrcnt[cent] = m;

    // aux outputs
    const int PO = BB * MM * H2D;            // pos_out offset (floats)
    const int BO = PO + BB * MM * 3;         // batch_out offset
    if (lane < 3 && PO + cent * 3 + lane < out_size)
        out[PO + cent * 3 + lane] = (lane == 0 ? qx[grp] : (lane == 1 ? qy[grp] : qz[grp]));
    if (lane == 3 && BO + cent < out_size)
        out[BO + cent] = (float)b;
}

// =====================================================================
// Kernel 3: gather + MLP(67->64 relu, 64->128 relu) + masked max.
// One centroid at a time per block; weights cached in smem; register-tiled
// fp32 GEMMs; 2 blocks/SM.
// =====================================================================
__global__ void __launch_bounds__(256, 2) conv_kernel(const float* __restrict__ x,
                                                      const float* __restrict__ pos,
                                                      const float* __restrict__ W1,
                                                      const float* __restrict__ b1,
                                                      const float* __restrict__ W2,
                                                      const float* __restrict__ b2,
                                                      float* __restrict__ out, int out_size)
{
    extern __shared__ float sm[];
    float* W1s  = sm;              // 67*64   = 4288
    float* b1s  = sm + 4288;       // 64
    float* W2s  = sm + 4352;       // 64*128  = 8192
    float* b2s  = sm + 12544;      // 128
    float* feat = sm + 12672;      // 64*68   = 4352
    float* h1s  = sm + 17024;      // 64*68   = 4352
    float* pmax = sm + 21376;      // 8*128   = 1024  -> total 22400 floats

    __shared__ int snbr[KK];
    __shared__ int scnt_s;

    const int tid = threadIdx.x;
    for (int i = tid; i < FDIM * H1D; i += 256) W1s[i] = W1[i];
    for (int i = tid; i < H1D * H2D; i += 256) W2s[i] = W2[i];
    if (tid < H1D) b1s[tid] = b1[tid];
    if (tid < H2D) b2s[tid] = b2[tid];
    __syncthreads();

    const int jg  = tid >> 4, og  = tid & 15;   // phase1: 4 rows x 4 cols
    const int jg2 = tid >> 5, og2 = tid & 31;   // phase2: 8 rows x 4 cols

    for (int c = blockIdx.x; c < BB * MM; c += gridDim.x) {
        const int bidx = c / MM;
        if (tid < KK) snbr[tid] = g_nbr[c * KK + tid];
        if (tid == KK) scnt_s = g_nbrcnt[c];
        __syncthreads();
        const int cnt = scnt_s;

        // gather x features (coalesced: 64 channels per neighbor row)
        const float* xb = x + (size_t)bidx * NP * CIN;
        for (int e = tid; e < KK * CIN; e += 256) {
            int j = e >> 6, ch = e & 63;
            int row = (j < cnt) ? snbr[j] : 0;
            float v = xb[(size_t)row * CIN + ch];
            feat[j * 68 + ch] = (j < cnt) ? v : 0.0f;
        }
        // relative positions
        if (tid < KK) {
            int j = tid;
            float q0 = g_q[c * 3 + 0], q1 = g_q[c * 3 + 1], q2 = g_q[c * 3 + 2];
            int row = (j < cnt) ? snbr[j] : 0;
            const float* pr = pos + ((size_t)bidx * NP + row) * 3;
            float rx = pr[0] - q0, ry = pr[1] - q1, rz = pr[2] - q2;
            feat[j * 68 + 64] = (j < cnt) ? rx : 0.0f;
            feat[j * 68 + 65] = (j < cnt) ? ry : 0.0f;
            feat[j * 68 + 66] = (j < cnt) ? rz : 0.0f;
            feat[j * 68 + 67] = 0.0f;
        }
        __syncthreads();

        // ---- phase 1: h1[64,64] = relu(feat @ W1 + b1) ----
        {
            float4 bv = *(const float4*)&b1s[og * 4];
            float acc[4][4];
#pragma unroll
            for (int jj = 0; jj < 4; jj++) {
                acc[jj][0] = bv.x; acc[jj][1] = bv.y; acc[jj][2] = bv.z; acc[jj][3] = bv.w;
            }
            for (int k = 0; k < FDIM; k++) {
                float f0 = feat[(jg * 4 + 0) * 68 + k];
                float f1 = feat[(jg * 4 + 1) * 68 + k];
                float f2 = feat[(jg * 4 + 2) * 68 + k];
                float f3 = feat[(jg * 4 + 3) * 68 + k];
                float4 w = *(const float4*)&W1s[k * 64 + og * 4];
                acc[0][0] += f0 * w.x; acc[0][1] += f0 * w.y; acc[0][2] += f0 * w.z; acc[0][3] += f0 * w.w;
                acc[1][0] += f1 * w.x; acc[1][1] += f1 * w.y; acc[1][2] += f1 * w.z; acc[1][3] += f1 * w.w;
                acc[2][0] += f2 * w.x; acc[2][1] += f2 * w.y; acc[2][2] += f2 * w.z; acc[2][3] += f2 * w.w;
                acc[3][0] += f3 * w.x; acc[3][1] += f3 * w.y; acc[3][2] += f3 * w.z; acc[3][3] += f3 * w.w;
            }
#pragma unroll
            for (int jj = 0; jj < 4; jj++) {
                float4 hv;
                hv.x = fmaxf(acc[jj][0], 0.0f);
                hv.y = fmaxf(acc[jj][1], 0.0f);
                hv.z = fmaxf(acc[jj][2], 0.0f);
                hv.w = fmaxf(acc[jj][3], 0.0f);
                *(float4*)&h1s[(jg * 4 + jj) * 68 + og * 4] = hv;
            }
        }
        __syncthreads();

        // ---- phase 2: h2 = relu(h1 @ W2 + b2), masked max over rows ----
        {
            float4 bv = *(const float4*)&b2s[og2 * 4];
            float a2[8][4];
#pragma unroll
            for (int jj = 0; jj < 8; jj++) {
                a2[jj][0] = bv.x; a2[jj][1] = bv.y; a2[jj][2] = bv.z; a2[jj][3] = bv.w;
            }
            for (int k = 0; k < H1D; k++) {
                float hv[8];
#pragma unroll
                for (int jj = 0; jj < 8; jj++) hv[jj] = h1s[(jg2 * 8 + jj) * 68 + k];
                float4 w = *(const float4*)&W2s[k * 128 + og2 * 4];
#pragma unroll
                for (int jj = 0; jj < 8; jj++) {
                    a2[jj][0] += hv[jj] * w.x;
                    a2[jj][1] += hv[jj] * w.y;
                    a2[jj][2] += hv[jj] * w.z;
                    a2[jj][3] += hv[jj] * w.w;
                }
            }
            float mx0 = -3.402823466e38f, mx1 = mx0, mx2 = mx0, mx3 = mx0;
#pragma unroll
            for (int jj = 0; jj < 8; jj++) {
                if (jg2 * 8 + jj < cnt) {
                    mx0 = fmaxf(mx0, fmaxf(a2[jj][0], 0.0f));
                    mx1 = fmaxf(mx1, fmaxf(a2[jj][1], 0.0f));
                    mx2 = fmaxf(mx2, fmaxf(a2[jj][2], 0.0f));
                    mx3 = fmaxf(mx3, fmaxf(a2[jj][3], 0.0f));
                }
            }
            float4 mv; mv.x = mx0; mv.y = mx1; mv.z = mx2; mv.w = mx3;
            *(float4*)&pmax[jg2 * 128 + og2 * 4] = mv;
        }
        __syncthreads();

        if (tid < H2D) {
            float r = pmax[tid];
#pragma unroll
            for (int g = 1; g < 8; g++) r = fmaxf(r, pmax[g * 128 + tid]);
            if (c * H2D + tid < out_size) out[c * H2D + tid] = r;
        }
        __syncthreads();   // feat/h1s reused next iteration
    }
}

// =====================================================================
extern "C" void kernel_launch(void* const* d_in, const int* in_sizes, int n_in,
                              void* d_out, int out_size)
{
    const float* x   = (const float*)d_in[0];
    const float* pos = (const float*)d_in[1];
    const float* W1  = (const float*)d_in[3];
    const float* b1  = (const float*)d_in[4];
    const float* W2  = (const float*)d_in[5];
    const float* b2  = (const float*)d_in[6];
    float* out = (float*)d_out;

    cudaFuncSetAttribute(fps_kernel, cudaFuncAttributeMaxDynamicSharedMemorySize, 3 * NP * 4);
    cudaFuncSetAttribute(conv_kernel, cudaFuncAttributeMaxDynamicSharedMemorySize, 22400 * 4);

    fps_kernel<<<BB, 512, 3 * NP * 4>>>(pos);
    nbr_kernel<<<BB * MM / 4, 256>>>(pos, out, out_size);
    conv_kernel<<<2048, 256, 22400 * 4>>>(x, pos, W1, b1, W2, b2, out, out_size);
}

// round 2
// speedup vs baseline: 1.2218x; 1.2218x over previous
#include <cuda_runtime.h>
#include <stdint.h>

#define NP   8192
#define MM   4096
#define BB   4
#define KK   64
#define CIN  64
#define FDIM 67
#define H1D  64
#define H2D  128
#define CAP  512

// exact same constant the reference compares against: f32(0.2*0.2 in double)
#define R2C ((float)(0.2 * 0.2))

// -------- scratch (device globals; no allocation allowed) --------
__device__ float g_q[BB * MM * 3];
__device__ int   g_nbr[BB * MM * KK];
__device__ int   g_nbrcnt[BB * MM];

// -------- packed f32x2 helpers (per-lane IEEE, bit-identical to scalar) -----
typedef unsigned long long u64;
__device__ __forceinline__ u64 pack2(float lo, float hi) {
    u64 r; asm("mov.b64 %0, {%1, %2};" : "=l"(r) : "f"(lo), "f"(hi)); return r;
}
__device__ __forceinline__ void unpack2(u64 v, float& lo, float& hi) {
    asm("mov.b64 {%0, %1}, %2;" : "=f"(lo), "=f"(hi) : "l"(v));
}
__device__ __forceinline__ u64 add2(u64 a, u64 b) {
    u64 r; asm("add.rn.f32x2 %0, %1, %2;" : "=l"(r) : "l"(a), "l"(b)); return r;
}
__device__ __forceinline__ u64 mul2(u64 a, u64 b) {
    u64 r; asm("mul.rn.f32x2 %0, %1, %2;" : "=l"(r) : "l"(a), "l"(b)); return r;
}
__device__ __forceinline__ u64 fma2(u64 a, u64 b, u64 c) {
    u64 r; asm("fma.rn.f32x2 %0, %1, %2, %3;" : "=l"(r) : "l"(a), "l"(b), "l"(c)); return r;
}

// =====================================================================
// Kernel 1: farthest point sampling. One block per cloud.
// Positions live in REGISTERS as packed f32x2 (pair i half h owns point
// g = tid + 512*(2i+h)). Distances in scalar regs for the winner scan.
// Update loop: 48 packed fma-pipe ops/thread, zero LDS. 2 barriers/step.
// =====================================================================
__global__ void __launch_bounds__(512) fps_kernel(const float* __restrict__ pos)
{
    extern __shared__ float sm[];
    float* sx = sm;
    float* sy = sm + NP;
    float* sz = sm + 2 * NP;
    __shared__ float rv[16];
    __shared__ int   s_widx[2];

    const int b = blockIdx.x, tid = threadIdx.x;
    const float* pb = pos + (size_t)b * NP * 3;

    for (int i = tid; i < NP; i += 512) {
        sx[i] = pb[3 * i + 0];
        sy[i] = pb[3 * i + 1];
        sz[i] = pb[3 * i + 2];
    }
    if (tid == 0) { s_widx[0] = 0x7FFFFFFF; s_widx[1] = 0x7FFFFFFF; }
    __syncthreads();

    // register-resident packed coordinates
    u64 X[8], Y[8], Z[8];
#pragma unroll
    for (int i = 0; i < 8; i++) {
        int g0 = tid + 512 * (2 * i);
        int g1 = tid + 512 * (2 * i + 1);
        X[i] = pack2(sx[g0], sx[g1]);
        Y[i] = pack2(sy[g0], sy[g1]);
        Z[i] = pack2(sz[g0], sz[g1]);
    }

    float cx = sx[0], cy = sy[0], cz = sz[0];
    float d[16];
    float tv = -1.0f;
    {
        u64 ncx = pack2(-cx, -cx), ncy = pack2(-cy, -cy), ncz = pack2(-cz, -cz);
#pragma unroll
        for (int i = 0; i < 8; i++) {
            u64 dx = add2(X[i], ncx);
            u64 dy = add2(Y[i], ncy);
            u64 dz = add2(Z[i], ncz);
            u64 nd = mul2(dx, dx);
            nd = fma2(dy, dy, nd);
            nd = fma2(dz, dz, nd);
            float n0, n1; unpack2(nd, n0, n1);
            d[2 * i + 0] = n0;
            d[2 * i + 1] = n1;
            tv = fmaxf(tv, fmaxf(n0, n1));
        }
    }
    if (tid == 0) {
        g_q[(b * MM) * 3 + 0] = cx;
        g_q[(b * MM) * 3 + 1] = cy;
        g_q[(b * MM) * 3 + 2] = cz;
    }

    for (int t = 1; t < MM; t++) {
        // warp-level max
        float wv = tv;
#pragma unroll
        for (int o = 16; o > 0; o >>= 1)
            wv = fmaxf(wv, __shfl_xor_sync(0xffffffffu, wv, o));
        if ((tid & 31) == 0) rv[tid >> 5] = wv;
        __syncthreads();                                  // (A)

        // every thread folds the 16 warp maxima (broadcast LDS)
        float vm = rv[0];
#pragma unroll
        for (int j = 1; j < 16; j++) vm = fmaxf(vm, rv[j]);

        const int cur = t & 1;
        if (tv == vm) {                                   // only potential winners
#pragma unroll
            for (int i = 0; i < 16; i++)
                if (d[i] == vm) atomicMin(&s_widx[cur], tid + 512 * i);
        }
        if (tid == 0) s_widx[cur ^ 1] = 0x7FFFFFFF;       // pre-reset other buffer
        __syncthreads();                                  // (B)

        const int w = s_widx[cur];
        cx = sx[w]; cy = sy[w]; cz = sz[w];
        if (tid == 0) {
            g_q[(b * MM + t) * 3 + 0] = cx;
            g_q[(b * MM + t) * 3 + 1] = cy;
            g_q[(b * MM + t) * 3 + 2] = cz;
        }

        // fused packed min-update + local max scan (register-only)
        u64 ncx = pack2(-cx, -cx), ncy = pack2(-cy, -cy), ncz = pack2(-cz, -cz);
        tv = -1.0f;
#pragma unroll
        for (int i = 0; i < 8; i++) {
            u64 dx = add2(X[i], ncx);
            u64 dy = add2(Y[i], ncy);
            u64 dz = add2(Z[i], ncz);
            u64 nd = mul2(dx, dx);
            nd = fma2(dy, dy, nd);
            nd = fma2(dz, dz, nd);
            float n0, n1; unpack2(nd, n0, n1);
            float d0 = fminf(d[2 * i + 0], n0);
            float d1 = fminf(d[2 * i + 1], n1);
            d[2 * i + 0] = d0;
            d[2 * i + 1] = d1;
            tv = fmaxf(tv, fmaxf(d0, d1));
        }
    }
}

// =====================================================================
// Kernel 2: radius + K-nearest via candidate compaction + bitonic sort on
// (d2_bits<<32 | idx) keys. 4 centroids per block (pos traffic /4).
// Also writes pos_out and batch_out sections of d_out.
// =====================================================================
__global__ void __launch_bounds__(256) nbr_kernel(const float* __restrict__ pos,
                                                  float* __restrict__ out, int out_size)
{
    __shared__ unsigned long long keys[4][CAP];
    __shared__ int scnt[4];
    __shared__ float qx[4], qy[4], qz[4];

    const int tid = threadIdx.x;
    const int cbase = blockIdx.x * 4;      // 4 centroids, same cloud (4 | MM)
    const int b = cbase / MM;

    if (tid < 4) {
        scnt[tid] = 0;
        qx[tid] = g_q[(cbase + tid) * 3 + 0];
        qy[tid] = g_q[(cbase + tid) * 3 + 1];
        qz[tid] = g_q[(cbase + tid) * 3 + 2];
    }
    __syncthreads();

    const float q0x = qx[0], q0y = qy[0], q0z = qz[0];
    const float q1x = qx[1], q1y = qy[1], q1z = qz[1];
    const float q2x = qx[2], q2y = qy[2], q2z = qz[2];
    const float q3x = qx[3], q3y = qy[3], q3z = qz[3];

    const float* pb = pos + (size_t)b * NP * 3;
    for (int i = tid; i < NP; i += 256) {
        float px = pb[3 * i + 0], py = pb[3 * i + 1], pz = pb[3 * i + 2];
        {
            float dx = q0x - px, dy = q0y - py, dz = q0z - pz;
            float d2 = dx * dx + dy * dy + dz * dz;
            if (d2 <= R2C) { int p = atomicAdd(&scnt[0], 1);
                if (p < CAP) keys[0][p] = ((unsigned long long)__float_as_uint(d2) << 32) | (unsigned)i; }
        }
        {
            float dx = q1x - px, dy = q1y - py, dz = q1z - pz;
            float d2 = dx * dx + dy * dy + dz * dz;
            if (d2 <= R2C) { int p = atomicAdd(&scnt[1], 1);
                if (p < CAP) keys[1][p] = ((unsigned long long)__float_as_uint(d2) << 32) | (unsigned)i; }
        }
        {
            float dx = q2x - px, dy = q2y - py, dz = q2z - pz;
            float d2 = dx * dx + dy * dy + dz * dz;
            if (d2 <= R2C) { int p = atomicAdd(&scnt[2], 1);
                if (p < CAP) keys[2][p] = ((unsigned long long)__float_as_uint(d2) << 32) | (unsigned)i; }
        }
        {
            float dx = q3x - px, dy = q3y - py, dz = q3z - pz;
            float d2 = dx * dx + dy * dy + dz * dz;
            if (d2 <= R2C) { int p = atomicAdd(&scnt[3], 1);
                if (p < CAP) keys[3][p] = ((unsigned long long)__float_as_uint(d2) << 32) | (unsigned)i; }
        }
    }
    __syncthreads();

    const int grp = tid >> 6, lane = tid & 63;
    const int n = min(scnt[grp], CAP);
    for (int i = lane; i < CAP; i += 64)
        if (i >= n) keys[grp][i] = 0xFFFFFFFFFFFFFFFFull;
    __syncthreads();

    // bitonic sort ascending — 4 groups in lockstep, one bar serves all
    for (int k = 2; k <= CAP; k <<= 1) {
        for (int j = k >> 1; j > 0; j >>= 1) {
            for (int i = lane; i < CAP; i += 64) {
                int ixj = i ^ j;
                if (ixj > i) {
                    unsigned long long a = keys[grp][i];
                    unsigned long long c = keys[grp][ixj];
                    bool up = ((i & k) == 0);
                    if ((a > c) == up) { keys[grp][i] = c; keys[grp][ixj] = a; }
                }
            }
            __syncthreads();
        }
    }

    const int m = min(n, KK);
    const int cent = cbase + grp;
    if (lane < KK)
        g_nbr[cent * KK + lane] = (lane < m) ? (int)(keys[grp][lane] & 0xFFFFFFFFu) : -1;
    if (lane == 0) g_nbrcnt[cent] = m;

    // aux outputs
    const int PO = BB * MM * H2D;            // pos_out offset (floats)
    const int BO = PO + BB * MM * 3;         // batch_out offset
    if (lane < 3 && PO + cent * 3 + lane < out_size)
        out[PO + cent * 3 + lane] = (lane == 0 ? qx[grp] : (lane == 1 ? qy[grp] : qz[grp]));
    if (lane == 3 && BO + cent < out_size)
        out[BO + cent] = (float)b;
}

// =====================================================================
// Kernel 3: gather + MLP(67->64 relu, 64->128 relu) + masked max.
// One centroid at a time per block; weights cached in smem; register-tiled
// fp32 GEMMs; 2 blocks/SM.
// =====================================================================
__global__ void __launch_bounds__(256, 2) conv_kernel(const float* __restrict__ x,
                                                      const float* __restrict__ pos,
                                                      const float* __restrict__ W1,
                                                      const float* __restrict__ b1,
                                                      const float* __restrict__ W2,
                                                      const float* __restrict__ b2,
                                                      float* __restrict__ out, int out_size)
{
    extern __shared__ float sm[];
    float* W1s  = sm;              // 67*64   = 4288
    float* b1s  = sm + 4288;       // 64
    float* W2s  = sm + 4352;       // 64*128  = 8192
    float* b2s  = sm + 12544;      // 128
    float* feat = sm + 12672;      // 64*68   = 4352
    float* h1s  = sm + 17024;      // 64*68   = 4352
    float* pmax = sm + 21376;      // 8*128   = 1024  -> total 22400 floats

    __shared__ int snbr[KK];
    __shared__ int scnt_s;

    const int tid = threadIdx.x;
    for (int i = tid; i < FDIM * H1D; i += 256) W1s[i] = W1[i];
    for (int i = tid; i < H1D * H2D; i += 256) W2s[i] = W2[i];
    if (tid < H1D) b1s[tid] = b1[tid];
    if (tid < H2D) b2s[tid] = b2[tid];
    __syncthreads();

    const int jg  = tid >> 4, og  = tid & 15;   // phase1: 4 rows x 4 cols
    const int jg2 = tid >> 5, og2 = tid & 31;   // phase2: 8 rows x 4 cols

    for (int c = blockIdx.x; c < BB * MM; c += gridDim.x) {
        const int bidx = c / MM;
        if (tid < KK) snbr[tid] = g_nbr[c * KK + tid];
        if (tid == KK) scnt_s = g_nbrcnt[c];
        __syncthreads();
        const int cnt = scnt_s;

        // gather x features (coalesced: 64 channels per neighbor row)
        const float* xb = x + (size_t)bidx * NP * CIN;
        for (int e = tid; e < KK * CIN; e += 256) {
            int j = e >> 6, ch = e & 63;
            int row = (j < cnt) ? snbr[j] : 0;
            float v = xb[(size_t)row * CIN + ch];
            feat[j * 68 + ch] = (j < cnt) ? v : 0.0f;
        }
        // relative positions
        if (tid < KK) {
            int j = tid;
            float q0 = g_q[c * 3 + 0], q1 = g_q[c * 3 + 1], q2 = g_q[c * 3 + 2];
            int row = (j < cnt) ? snbr[j] : 0;
            const float* pr = pos + ((size_t)bidx * NP + row) * 3;
            float rx = pr[0] - q0, ry = pr[1] - q1, rz = pr[2] - q2;
            feat[j * 68 + 64] = (j < cnt) ? rx : 0.0f;
            feat[j * 68 + 65] = (j < cnt) ? ry : 0.0f;
            feat[j * 68 + 66] = (j < cnt) ? rz : 0.0f;
            feat[j * 68 + 67] = 0.0f;
        }
        __syncthreads();

        // ---- phase 1: h1[64,64] = relu(feat @ W1 + b1) ----
        {
            float4 bv = *(const float4*)&b1s[og * 4];
            float acc[4][4];
#pragma unroll
            for (int jj = 0; jj < 4; jj++) {
                acc[jj][0] = bv.x; acc[jj][1] = bv.y; acc[jj][2] = bv.z; acc[jj][3] = bv.w;
            }
            for (int k = 0; k < FDIM; k++) {
                float f0 = feat[(jg * 4 + 0) * 68 + k];
                float f1 = feat[(jg * 4 + 1) * 68 + k];
                float f2 = feat[(jg * 4 + 2) * 68 + k];
                float f3 = feat[(jg * 4 + 3) * 68 + k];
                float4 w = *(const float4*)&W1s[k * 64 + og * 4];
                acc[0][0] += f0 * w.x; acc[0][1] += f0 * w.y; acc[0][2] += f0 * w.z; acc[0][3] += f0 * w.w;
                acc[1][0] += f1 * w.x; acc[1][1] += f1 * w.y; acc[1][2] += f1 * w.z; acc[1][3] += f1 * w.w;
                acc[2][0] += f2 * w.x; acc[2][1] += f2 * w.y; acc[2][2] += f2 * w.z; acc[2][3] += f2 * w.w;
                acc[3][0] += f3 * w.x; acc[3][1] += f3 * w.y; acc[3][2] += f3 * w.z; acc[3][3] += f3 * w.w;
            }
#pragma unroll
            for (int jj = 0; jj < 4; jj++) {
                float4 hv;
                hv.x = fmaxf(acc[jj][0], 0.0f);
                hv.y = fmaxf(acc[jj][1], 0.0f);
                hv.z = fmaxf(acc[jj][2], 0.0f);
                hv.w = fmaxf(acc[jj][3], 0.0f);
                *(float4*)&h1s[(jg * 4 + jj) * 68 + og * 4] = hv;
            }
        }
        __syncthreads();

        // ---- phase 2: h2 = relu(h1 @ W2 + b2), masked max over rows ----
        {
            float4 bv = *(const float4*)&b2s[og2 * 4];
            float a2[8][4];
#pragma unroll
            for (int jj = 0; jj < 8; jj++) {
                a2[jj][0] = bv.x; a2[jj][1] = bv.y; a2[jj][2] = bv.z; a2[jj][3] = bv.w;
            }
            for (int k = 0; k < H1D; k++) {
                float hv[8];
#pragma unroll
                for (int jj = 0; jj < 8; jj++) hv[jj] = h1s[(jg2 * 8 + jj) * 68 + k];
                float4 w = *(const float4*)&W2s[k * 128 + og2 * 4];
#pragma unroll
                for (int jj = 0; jj < 8; jj++) {
                    a2[jj][0] += hv[jj] * w.x;
                    a2[jj][1] += hv[jj] * w.y;
                    a2[jj][2] += hv[jj] * w.z;
                    a2[jj][3] += hv[jj] * w.w;
                }
            }
            float mx0 = -3.402823466e38f, mx1 = mx0, mx2 = mx0, mx3 = mx0;
#pragma unroll
            for (int jj = 0; jj < 8; jj++) {
                if (jg2 * 8 + jj < cnt) {
                    mx0 = fmaxf(mx0, fmaxf(a2[jj][0], 0.0f));
                    mx1 = fmaxf(mx1, fmaxf(a2[jj][1], 0.0f));
                    mx2 = fmaxf(mx2, fmaxf(a2[jj][2], 0.0f));
                    mx3 = fmaxf(mx3, fmaxf(a2[jj][3], 0.0f));
                }
            }
            float4 mv; mv.x = mx0; mv.y = mx1; mv.z = mx2; mv.w = mx3;
            *(float4*)&pmax[jg2 * 128 + og2 * 4] = mv;
        }
        __syncthreads();

        if (tid < H2D) {
            float r = pmax[tid];
#pragma unroll
            for (int g = 1; g < 8; g++) r = fmaxf(r, pmax[g * 128 + tid]);
            if (c * H2D + tid < out_size) out[c * H2D + tid] = r;
        }
        __syncthreads();   // feat/h1s reused next iteration
    }
}

// =====================================================================
extern "C" void kernel_launch(void* const* d_in, const int* in_sizes, int n_in,
                              void* d_out, int out_size)
{
    const float* x   = (const float*)d_in[0];
    const float* pos = (const float*)d_in[1];
    const float* W1  = (const float*)d_in[3];
    const float* b1  = (const float*)d_in[4];
    const float* W2  = (const float*)d_in[5];
    const float* b2  = (const float*)d_in[6];
    float* out = (float*)d_out;

    cudaFuncSetAttribute(fps_kernel, cudaFuncAttributeMaxDynamicSharedMemorySize, 3 * NP * 4);
    cudaFuncSetAttribute(conv_kernel, cudaFuncAttributeMaxDynamicSharedMemorySize, 22400 * 4);

    fps_kernel<<<BB, 512, 3 * NP * 4>>>(pos);
    nbr_kernel<<<BB * MM / 4, 256>>>(pos, out, out_size);
    conv_kernel<<<2048, 256, 22400 * 4>>>(x, pos, W1, b1, W2, b2, out, out_size);
}

// round 4
// speedup vs baseline: 1.4965x; 1.2248x over previous
#include <cuda_runtime.h>
#include <stdint.h>

#define NP   8192
#define MM   4096
#define BB   4
#define KK   64
#define CIN  64
#define FDIM 67
#define H1D  64
#define H2D  128
#define CAP  512

// exact same constant the reference compares against: f32(0.2*0.2 in double)
#define R2C ((float)(0.2 * 0.2))

// -------- scratch (device globals; no allocation allowed) --------
__device__ float g_q[BB * MM * 3];
__device__ int   g_nbr[BB * MM * KK];
__device__ int   g_nbrcnt[BB * MM];

// -------- packed f32x2 helpers (per-lane IEEE, bit-identical to scalar) -----
typedef unsigned long long u64;
__device__ __forceinline__ u64 pack2(float lo, float hi) {
    u64 r; asm("mov.b64 %0, {%1, %2};" : "=l"(r) : "f"(lo), "f"(hi)); return r;
}
__device__ __forceinline__ void unpack2(u64 v, float& lo, float& hi) {
    asm("mov.b64 {%0, %1}, %2;" : "=f"(lo), "=f"(hi) : "l"(v));
}
__device__ __forceinline__ u64 add2(u64 a, u64 b) {
    u64 r; asm("add.rn.f32x2 %0, %1, %2;" : "=l"(r) : "l"(a), "l"(b)); return r;
}
__device__ __forceinline__ u64 mul2(u64 a, u64 b) {
    u64 r; asm("mul.rn.f32x2 %0, %1, %2;" : "=l"(r) : "l"(a), "l"(b)); return r;
}
__device__ __forceinline__ u64 fma2(u64 a, u64 b, u64 c) {
    u64 r; asm("fma.rn.f32x2 %0, %1, %2, %3;" : "=l"(r) : "l"(a), "l"(b), "l"(c)); return r;
}
__device__ __forceinline__ unsigned redux_max(unsigned v) {
    unsigned r; asm("redux.sync.max.u32 %0, %1, 0xffffffff;" : "=r"(r) : "r"(v)); return r;
}
__device__ __forceinline__ int spread3(int v) {
    return (v & 1) | ((v & 2) << 2) | ((v & 4) << 4);
}
__device__ __forceinline__ int cell_of(float px, float py, float pz) {
    int cx = min(7, max(0, (int)(px * 8.0f)));
    int cy = min(7, max(0, (int)(py * 8.0f)));
    int cz = min(7, max(0, (int)(pz * 8.0f)));
    return spread3(cx) | (spread3(cy) << 1) | (spread3(cz) << 2);
}

// =====================================================================
// Kernel 1: farthest point sampling, one block per cloud.
// Morton-sorted ownership (registers + bbox skip) for the update loop,
// but tie-breaking and winner lookup use ORIGINAL indices/order, so the
// selected sequence is bit-identical to the reference (jnp.argmax picks
// the first maximal original index; ties DO occur).
// =====================================================================
__global__ void __launch_bounds__(512, 1) fps_kernel(const float* __restrict__ pos)
{
    extern __shared__ float smf[];
    float* sxo = smf;                 // [NP] original order
    float* syo = smf + NP;
    float* szo = smf + 2 * NP;
    float* sxs = smf + 3 * NP;        // [NP] Morton-sorted
    float* sys = smf + 4 * NP;
    float* szs = smf + 5 * NP;
    unsigned short* sidx = (unsigned short*)(smf + 6 * NP);   // sorted slot -> orig idx
    int* cnt = (int*)(sidx + NP);     // [512] counts -> cursors

    __shared__ unsigned rv[16];
    __shared__ int wsum[16];
    __shared__ int s_widx[2];

    const int b = blockIdx.x, tid = threadIdx.x;
    const int lane = tid & 31, warp = tid >> 5;
    const float* pb = pos + (size_t)b * NP * 3;

    // ---- pass 1: load original order + cell counts ----
    cnt[tid] = 0;
    if (tid == 0) { s_widx[0] = 0x7FFFFFFF; s_widx[1] = 0x7FFFFFFF; }
    __syncthreads();
    for (int i = tid; i < NP; i += 512) {
        float px = pb[3 * i + 0], py = pb[3 * i + 1], pz = pb[3 * i + 2];
        sxo[i] = px; syo[i] = py; szo[i] = pz;
        atomicAdd(&cnt[cell_of(px, py, pz)], 1);
    }
    __syncthreads();

    // ---- exclusive prefix sum over 512 counts ----
    int myc = cnt[tid];
    int v = myc;
#pragma unroll
    for (int o = 1; o < 32; o <<= 1) {
        int n = __shfl_up_sync(0xffffffffu, v, o);
        if (lane >= o) v += n;
    }
    if (lane == 31) wsum[warp] = v;
    __syncthreads();
    int woff = 0;
#pragma unroll
    for (int j = 0; j < 16; j++) woff += (j < warp) ? wsum[j] : 0;
    const int start = woff + v - myc;
    __syncthreads();
    cnt[tid] = start;     // becomes scatter cursor
    __syncthreads();

    // ---- pass 2: scatter into Morton order (record orig index) ----
    for (int i = tid; i < NP; i += 512) {
        float px = sxo[i], py = syo[i], pz = szo[i];
        int slot = atomicAdd(&cnt[cell_of(px, py, pz)], 1);
        sxs[slot] = px; sys[slot] = py; szs[slot] = pz;
        sidx[slot] = (unsigned short)i;
    }
    __syncthreads();

    // ---- registers: 16 sorted points per thread + bbox + orig indices ----
    const int base = tid * 16;
    u64 X[8], Y[8], Z[8];
    unsigned idx2[8];
    float lox = 1e30f, loy = 1e30f, loz = 1e30f;
    float hix = -1e30f, hiy = -1e30f, hiz = -1e30f;
#pragma unroll
    for (int i = 0; i < 8; i++) {
        float x0 = sxs[base + 2 * i], x1 = sxs[base + 2 * i + 1];
        float y0 = sys[base + 2 * i], y1 = sys[base + 2 * i + 1];
        float z0 = szs[base + 2 * i], z1 = szs[base + 2 * i + 1];
        X[i] = pack2(x0, x1); Y[i] = pack2(y0, y1); Z[i] = pack2(z0, z1);
        idx2[i] = (unsigned)sidx[base + 2 * i] | ((unsigned)sidx[base + 2 * i + 1] << 16);
        lox = fminf(lox, fminf(x0, x1)); hix = fmaxf(hix, fmaxf(x0, x1));
        loy = fminf(loy, fminf(y0, y1)); hiy = fmaxf(hiy, fmaxf(y0, y1));
        loz = fminf(loz, fminf(z0, z1)); hiz = fmaxf(hiz, fmaxf(z0, z1));
    }

    // ---- seed: original point 0 ----
    float cx = sxo[0], cy = syo[0], cz = szo[0];
    float d[16];
    float tv = -1.0f;
    {
        u64 ncx = pack2(-cx, -cx), ncy = pack2(-cy, -cy), ncz = pack2(-cz, -cz);
#pragma unroll
        for (int i = 0; i < 8; i++) {
            u64 dx = add2(X[i], ncx);
            u64 dy = add2(Y[i], ncy);
            u64 dz = add2(Z[i], ncz);
            u64 nd = mul2(dx, dx);
            nd = fma2(dy, dy, nd);
            nd = fma2(dz, dz, nd);
            float n0, n1; unpack2(nd, n0, n1);
            d[2 * i + 0] = n0;
            d[2 * i + 1] = n1;
            tv = fmaxf(tv, fmaxf(n0, n1));
        }
    }
    if (tid == 0) {
        g_q[(b * MM) * 3 + 0] = cx;
        g_q[(b * MM) * 3 + 1] = cy;
        g_q[(b * MM) * 3 + 2] = cz;
    }

    for (int t = 1; t < MM; t++) {
        // block max of tv via u32 redux (d2 >= 0 -> bit order == float order)
        const unsigned tb = __float_as_uint(tv);
        unsigned wmax = redux_max(tb);
        if (lane == 0) rv[warp] = wmax;
        __syncthreads();                                  // (A)

        unsigned vmb = rv[0];
#pragma unroll
        for (int j = 1; j < 16; j++) vmb = max(vmb, rv[j]);
        const float vm = __uint_as_float(vmb);

        const int cur = t & 1;
        if (tb == vmb) {                                  // only potential winners
#pragma unroll
            for (int i = 0; i < 16; i++)
                if (d[i] == vm) {
                    int orig = (int)((idx2[i >> 1] >> ((i & 1) * 16)) & 0xFFFFu);
                    atomicMin(&s_widx[cur], orig);        // reference tie-break
                }
        }
        if (tid == 0) s_widx[cur ^ 1] = 0x7FFFFFFF;       // pre-reset other buffer
        __syncthreads();                                  // (B)

        const int w = s_widx[cur];                        // original index
        cx = sxo[w]; cy = syo[w]; cz = szo[w];
        if (tid == 0) {
            g_q[(b * MM + t) * 3 + 0] = cx;
            g_q[(b * MM + t) * 3 + 1] = cy;
            g_q[(b * MM + t) * 3 + 2] = cz;
        }

        // bbox lower-bound distance: skip update if it can't lower any d
        float ddx = fmaxf(fmaxf(lox - cx, cx - hix), 0.0f);
        float ddy = fmaxf(fmaxf(loy - cy, cy - hiy), 0.0f);
        float ddz = fmaxf(fmaxf(loz - cz, cz - hiz), 0.0f);
        float dm2 = ddx * ddx;
        dm2 = fmaf(ddy, ddy, dm2);
        dm2 = fmaf(ddz, ddz, dm2);

        if (dm2 * 0.99999f < tv) {
            u64 ncx = pack2(-cx, -cx), ncy = pack2(-cy, -cy), ncz = pack2(-cz, -cz);
            float ntv = -1.0f;
#pragma unroll
            for (int i = 0; i < 8; i++) {
                u64 dx = add2(X[i], ncx);
                u64 dy = add2(Y[i], ncy);
                u64 dz = add2(Z[i], ncz);
                u64 nd = mul2(dx, dx);
                nd = fma2(dy, dy, nd);
                nd = fma2(dz, dz, nd);
                float n0, n1; unpack2(nd, n0, n1);
                float d0 = fminf(d[2 * i + 0], n0);
                float d1 = fminf(d[2 * i + 1], n1);
                d[2 * i + 0] = d0;
                d[2 * i + 1] = d1;
                ntv = fmaxf(ntv, fmaxf(d0, d1));
            }
            tv = ntv;
        }
    }
}

// =====================================================================
// Kernel 2: radius + K-nearest via candidate compaction + bitonic sort on
// (d2_bits<<32 | idx) keys. 4 centroids per block (pos traffic /4).
// Also writes pos_out and batch_out sections of d_out.
// =====================================================================
__global__ void __launch_bounds__(256) nbr_kernel(const float* __restrict__ pos,
                                                  float* __restrict__ out, int out_size)
{
    __shared__ unsigned long long keys[4][CAP];
    __shared__ int scnt[4];
    __shared__ float qx[4], qy[4], qz[4];

    const int tid = threadIdx.x;
    const int cbase = blockIdx.x * 4;      // 4 centroids, same cloud (4 | MM)
    const int b = cbase / MM;

    if (tid < 4) {
        scnt[tid] = 0;
        qx[tid] = g_q[(cbase + tid) * 3 + 0];
        qy[tid] = g_q[(cbase + tid) * 3 + 1];
        qz[tid] = g_q[(cbase + tid) * 3 + 2];
    }
    __syncthreads();

    const float q0x = qx[0], q0y = qy[0], q0z = qz[0];
    const float q1x = qx[1], q1y = qy[1], q1z = qz[1];
    const float q2x = qx[2], q2y = qy[2], q2z = qz[2];
    const float q3x = qx[3], q3y = qy[3], q3z = qz[3];

    const float* pb = pos + (size_t)b * NP * 3;
    for (int i = tid; i < NP; i += 256) {
        float px = pb[3 * i + 0], py = pb[3 * i + 1], pz = pb[3 * i + 2];
        {
            float dx = q0x - px, dy = q0y - py, dz = q0z - pz;
            float d2 = dx * dx + dy * dy + dz * dz;
            if (d2 <= R2C) { int p = atomicAdd(&scnt[0], 1);
                if (p < CAP) keys[0][p] = ((unsigned long long)__float_as_uint(d2) << 32) | (unsigned)i; }
        }
        {
            float dx = q1x - px, dy = q1y - py, dz = q1z - pz;
            float d2 = dx * dx + dy * dy + dz * dz;
            if (d2 <= R2C) { int p = atomicAdd(&scnt[1], 1);
                if (p < CAP) keys[1][p] = ((unsigned long long)__float_as_uint(d2) << 32) | (unsigned)i; }
        }
        {
            float dx = q2x - px, dy = q2y - py, dz = q2z - pz;
            float d2 = dx * dx + dy * dy + dz * dz;
            if (d2 <= R2C) { int p = atomicAdd(&scnt[2], 1);
                if (p < CAP) keys[2][p] = ((unsigned long long)__float_as_uint(d2) << 32) | (unsigned)i; }
        }
        {
            float dx = q3x - px, dy = q3y - py, dz = q3z - pz;
            float d2 = dx * dx + dy * dy + dz * dz;
            if (d2 <= R2C) { int p = atomicAdd(&scnt[3], 1);
                if (p < CAP) keys[3][p] = ((unsigned long long)__float_as_uint(d2) << 32) | (unsigned)i; }
        }
    }
    __syncthreads();

    const int grp = tid >> 6, lane = tid & 63;
    const int n = min(scnt[grp], CAP);
    for (int i = lane; i < CAP; i += 64)
        if (i >= n) keys[grp][i] = 0xFFFFFFFFFFFFFFFFull;
    __syncthreads();

    // bitonic sort ascending — 4 groups in lockstep, one bar serves all
    for (int k = 2; k <= CAP; k <<= 1) {
        for (int j = k >> 1; j > 0; j >>= 1) {
            for (int i = lane; i < CAP; i += 64) {
                int ixj = i ^ j;
                if (ixj > i) {
                    unsigned long long a = keys[grp][i];
                    unsigned long long c = keys[grp][ixj];
                    bool up = ((i & k) == 0);
                    if ((a > c) == up) { keys[grp][i] = c; keys[grp][ixj] = a; }
                }
            }
            __syncthreads();
        }
    }

    const int m = min(n, KK);
    const int cent = cbase + grp;
    if (lane < KK)
        g_nbr[cent * KK + lane] = (lane < m) ? (int)(keys[grp][lane] & 0xFFFFFFFFu) : -1;
    if (lane == 0) g_nbrcnt[cent] = m;

    // aux outputs
    const int PO = BB * MM * H2D;            // pos_out offset (floats)
    const int BO = PO + BB * MM * 3;         // batch_out offset
    if (lane < 3 && PO + cent * 3 + lane < out_size)
        out[PO + cent * 3 + lane] = (lane == 0 ? qx[grp] : (lane == 1 ? qy[grp] : qz[grp]));
    if (lane == 3 && BO + cent < out_size)
        out[BO + cent] = (float)b;
}

// =====================================================================
// Kernel 3: gather + MLP(67->64 relu, 64->128 relu) + masked max.
// One centroid at a time per block; weights cached in smem; register-tiled
// fp32 GEMMs; 2 blocks/SM.
// =====================================================================
__global__ void __launch_bounds__(256, 2) conv_kernel(const float* __restrict__ x,
                                                      const float* __restrict__ pos,
                                                      const float* __restrict__ W1,
                                                      const float* __restrict__ b1,
                                                      const float* __restrict__ W2,
                                                      const float* __restrict__ b2,
                                                      float* __restrict__ out, int out_size)
{
    extern __shared__ float sm[];
    float* W1s  = sm;              // 67*64   = 4288
    float* b1s  = sm + 4288;       // 64
    float* W2s  = sm + 4352;       // 64*128  = 8192
    float* b2s  = sm + 12544;      // 128
    float* feat = sm + 12672;      // 64*68   = 4352
    float* h1s  = sm + 17024;      // 64*68   = 4352
    float* pmax = sm + 21376;      // 8*128   = 1024  -> total 22400 floats

    __shared__ int snbr[KK];
    __shared__ int scnt_s;

    const int tid = threadIdx.x;
    for (int i = tid; i < FDIM * H1D; i += 256) W1s[i] = W1[i];
    for (int i = tid; i < H1D * H2D; i += 256) W2s[i] = W2[i];
    if (tid < H1D) b1s[tid] = b1[tid];
    if (tid < H2D) b2s[tid] = b2[tid];
    __syncthreads();

    const int jg  = tid >> 4, og  = tid & 15;   // phase1: 4 rows x 4 cols
    const int jg2 = tid >> 5, og2 = tid & 31;   // phase2: 8 rows x 4 cols

    for (int c = blockIdx.x; c < BB * MM; c += gridDim.x) {
        const int bidx = c / MM;
        if (tid < KK) snbr[tid] = g_nbr[c * KK + tid];
        if (tid == KK) scnt_s = g_nbrcnt[c];
        __syncthreads();
        const int cnt = scnt_s;

        // gather x features (coalesced: 64 channels per neighbor row)
        const float* xb = x + (size_t)bidx * NP * CIN;
        for (int e = tid; e < KK * CIN; e += 256) {
            int j = e >> 6, ch = e & 63;
            int row = (j < cnt) ? snbr[j] : 0;
            float v = xb[(size_t)row * CIN + ch];
            feat[j * 68 + ch] = (j < cnt) ? v : 0.0f;
        }
        // relative positions
        if (tid < KK) {
            int j = tid;
            float q0 = g_q[c * 3 + 0], q1 = g_q[c * 3 + 1], q2 = g_q[c * 3 + 2];
            int row = (j < cnt) ? snbr[j] : 0;
            const float* pr = pos + ((size_t)bidx * NP + row) * 3;
            float rx = pr[0] - q0, ry = pr[1] - q1, rz = pr[2] - q2;
            feat[j * 68 + 64] = (j < cnt) ? rx : 0.0f;
            feat[j * 68 + 65] = (j < cnt) ? ry : 0.0f;
            feat[j * 68 + 66] = (j < cnt) ? rz : 0.0f;
            feat[j * 68 + 67] = 0.0f;
        }
        __syncthreads();

        // ---- phase 1: h1[64,64] = relu(feat @ W1 + b1) ----
        {
            float4 bv = *(const float4*)&b1s[og * 4];
            float acc[4][4];
#pragma unroll
            for (int jj = 0; jj < 4; jj++) {
                acc[jj][0] = bv.x; acc[jj][1] = bv.y; acc[jj][2] = bv.z; acc[jj][3] = bv.w;
            }
            for (int k = 0; k < FDIM; k++) {
                float f0 = feat[(jg * 4 + 0) * 68 + k];
                float f1 = feat[(jg * 4 + 1) * 68 + k];
                float f2 = feat[(jg * 4 + 2) * 68 + k];
                float f3 = feat[(jg * 4 + 3) * 68 + k];
                float4 w = *(const float4*)&W1s[k * 64 + og * 4];
                acc[0][0] += f0 * w.x; acc[0][1] += f0 * w.y; acc[0][2] += f0 * w.z; acc[0][3] += f0 * w.w;
                acc[1][0] += f1 * w.x; acc[1][1] += f1 * w.y; acc[1][2] += f1 * w.z; acc[1][3] += f1 * w.w;
                acc[2][0] += f2 * w.x; acc[2][1] += f2 * w.y; acc[2][2] += f2 * w.z; acc[2][3] += f2 * w.w;
                acc[3][0] += f3 * w.x; acc[3][1] += f3 * w.y; acc[3][2] += f3 * w.z; acc[3][3] += f3 * w.w;
            }
#pragma unroll
            for (int jj = 0; jj < 4; jj++) {
                float4 hv;
                hv.x = fmaxf(acc[jj][0], 0.0f);
                hv.y = fmaxf(acc[jj][1], 0.0f);
                hv.z = fmaxf(acc[jj][2], 0.0f);
                hv.w = fmaxf(acc[jj][3], 0.0f);
                *(float4*)&h1s[(jg * 4 + jj) * 68 + og * 4] = hv;
            }
        }
        __syncthreads();

        // ---- phase 2: h2 = relu(h1 @ W2 + b2), masked max over rows ----
        {
            float4 bv = *(const float4*)&b2s[og2 * 4];
            float a2[8][4];
#pragma unroll
            for (int jj = 0; jj < 8; jj++) {
                a2[jj][0] = bv.x; a2[jj][1] = bv.y; a2[jj][2] = bv.z; a2[jj][3] = bv.w;
            }
            for (int k = 0; k < H1D; k++) {
                float hv[8];
#pragma unroll
                for (int jj = 0; jj < 8; jj++) hv[jj] = h1s[(jg2 * 8 + jj) * 68 + k];
                float4 w = *(const float4*)&W2s[k * 128 + og2 * 4];
#pragma unroll
                for (int jj = 0; jj < 8; jj++) {
                    a2[jj][0] += hv[jj] * w.x;
                    a2[jj][1] += hv[jj] * w.y;
                    a2[jj][2] += hv[jj] * w.z;
                    a2[jj][3] += hv[jj] * w.w;
                }
            }
            float mx0 = -3.402823466e38f, mx1 = mx0, mx2 = mx0, mx3 = mx0;
#pragma unroll
            for (int jj = 0; jj < 8; jj++) {
                if (jg2 * 8 + jj < cnt) {
                    mx0 = fmaxf(mx0, fmaxf(a2[jj][0], 0.0f));
                    mx1 = fmaxf(mx1, fmaxf(a2[jj][1], 0.0f));
                    mx2 = fmaxf(mx2, fmaxf(a2[jj][2], 0.0f));
                    mx3 = fmaxf(mx3, fmaxf(a2[jj][3], 0.0f));
                }
            }
            float4 mv; mv.x = mx0; mv.y = mx1; mv.z = mx2; mv.w = mx3;
            *(float4*)&pmax[jg2 * 128 + og2 * 4] = mv;
        }
        __syncthreads();

        if (tid < H2D) {
            float r = pmax[tid];
#pragma unroll
            for (int g = 1; g < 8; g++) r = fmaxf(r, pmax[g * 128 + tid]);
            if (c * H2D + tid < out_size) out[c * H2D + tid] = r;
        }
        __syncthreads();   // feat/h1s reused next iteration
    }
}

// =====================================================================
extern "C" void kernel_launch(void* const* d_in, const int* in_sizes, int n_in,
                              void* d_out, int out_size)
{
    const float* x   = (const float*)d_in[0];
    const float* pos = (const float*)d_in[1];
    const float* W1  = (const float*)d_in[3];
    const float* b1  = (const float*)d_in[4];
    const float* W2  = (const float*)d_in[5];
    const float* b2  = (const float*)d_in[6];
    float* out = (float*)d_out;

    const int FPS_SMEM = 6 * NP * 4 + NP * 2 + 512 * 4;   // 2x pos copies + sidx + counters
    cudaFuncSetAttribute(fps_kernel, cudaFuncAttributeMaxDynamicSharedMemorySize, FPS_SMEM);
    cudaFuncSetAttribute(conv_kernel, cudaFuncAttributeMaxDynamicSharedMemorySize, 22400 * 4);

    fps_kernel<<<BB, 512, FPS_SMEM>>>(pos);
    nbr_kernel<<<BB * MM / 4, 256>>>(pos, out, out_size);
    conv_kernel<<<2048, 256, 22400 * 4>>>(x, pos, W1, b1, W2, b2, out, out_size);
}

// round 5
// speedup vs baseline: 1.9550x; 1.3064x over previous
#include <cuda_runtime.h>
#include <stdint.h>

#define NP   8192
#define MM   4096
#define BB   4
#define KK   64
#define CIN  64
#define FDIM 67
#define H1D  64
#define H2D  128
#define CAP  512
#define NWORK 144

// exact same constant the reference compares against: f32(0.2*0.2 in double)
#define R2C ((float)(0.2 * 0.2))

// -------- scratch (device globals; no allocation allowed) --------
__device__ float g_q[BB * MM * 3];
__device__ int   g_prog[BB];

// -------- packed f32x2 helpers (per-lane IEEE, bit-identical to scalar) -----
typedef unsigned long long u64;
__device__ __forceinline__ u64 pack2(float lo, float hi) {
    u64 r; asm("mov.b64 %0, {%1, %2};" : "=l"(r) : "f"(lo), "f"(hi)); return r;
}
__device__ __forceinline__ void unpack2(u64 v, float& lo, float& hi) {
    asm("mov.b64 {%0, %1}, %2;" : "=f"(lo), "=f"(hi) : "l"(v));
}
__device__ __forceinline__ u64 add2(u64 a, u64 b) {
    u64 r; asm("add.rn.f32x2 %0, %1, %2;" : "=l"(r) : "l"(a), "l"(b)); return r;
}
__device__ __forceinline__ u64 mul2(u64 a, u64 b) {
    u64 r; asm("mul.rn.f32x2 %0, %1, %2;" : "=l"(r) : "l"(a), "l"(b)); return r;
}
__device__ __forceinline__ u64 fma2(u64 a, u64 b, u64 c) {
    u64 r; asm("fma.rn.f32x2 %0, %1, %2, %3;" : "=l"(r) : "l"(a), "l"(b), "l"(c)); return r;
}
__device__ __forceinline__ unsigned redux_max(unsigned v) {
    unsigned r; asm("redux.sync.max.u32 %0, %1, 0xffffffff;" : "=r"(r) : "r"(v)); return r;
}
__device__ __forceinline__ int spread3(int v) {
    return (v & 1) | ((v & 2) << 2) | ((v & 4) << 4);
}
__device__ __forceinline__ int cell_of(float px, float py, float pz) {
    int cx = min(7, max(0, (int)(px * 8.0f)));
    int cy = min(7, max(0, (int)(py * 8.0f)));
    int cz = min(7, max(0, (int)(pz * 8.0f)));
    return spread3(cx) | (spread3(cy) << 1) | (spread3(cz) << 2);
}

__global__ void reset_kernel() {
    if (threadIdx.x < BB) g_prog[threadIdx.x] = 0;
}

// =====================================================================
// Fused persistent kernel.
// Blocks 0..3: FPS producer (one per cloud), publishing g_prog every 16.
// Blocks 4..147: workers — per centroid: spin-wait, radius scan + exact
// top-K (bitonic on (d2,idx) keys), gather, MLP (FFMA2-packed), masked max.
// All 148 blocks co-resident (210KB smem -> 1 block/SM).
// =====================================================================
__global__ void __launch_bounds__(512, 1) fused_kernel(
    const float* __restrict__ x, const float* __restrict__ pos,
    const float* __restrict__ W1, const float* __restrict__ b1,
    const float* __restrict__ W2, const float* __restrict__ b2,
    float* __restrict__ out, int out_size)
{
    extern __shared__ float smf[];
    const int tid = threadIdx.x;

    if (blockIdx.x < BB) {
        // ======================= FPS producer =======================
        float* sxo = smf;                 // [NP] original order
        float* syo = smf + NP;
        float* szo = smf + 2 * NP;
        float* sxs = smf + 3 * NP;        // [NP] Morton-sorted
        float* sys = smf + 4 * NP;
        float* szs = smf + 5 * NP;
        unsigned short* sidx = (unsigned short*)(smf + 6 * NP);   // slot -> orig idx
        int* cnt = (int*)(sidx + NP);     // [512]

        __shared__ unsigned rv[16];
        __shared__ int wsum[16];
        __shared__ int s_widx[2];

        const int b = blockIdx.x;
        const int lane = tid & 31, warp = tid >> 5;
        const float* pb = pos + (size_t)b * NP * 3;

        cnt[tid] = 0;
        if (tid == 0) { s_widx[0] = 0x7FFFFFFF; s_widx[1] = 0x7FFFFFFF; }
        __syncthreads();
        for (int i = tid; i < NP; i += 512) {
            float px = pb[3 * i + 0], py = pb[3 * i + 1], pz = pb[3 * i + 2];
            sxo[i] = px; syo[i] = py; szo[i] = pz;
            atomicAdd(&cnt[cell_of(px, py, pz)], 1);
        }
        __syncthreads();

        int myc = cnt[tid];
        int v = myc;
#pragma unroll
        for (int o = 1; o < 32; o <<= 1) {
            int n = __shfl_up_sync(0xffffffffu, v, o);
            if (lane >= o) v += n;
        }
        if (lane == 31) wsum[warp] = v;
        __syncthreads();
        int woff = 0;
#pragma unroll
        for (int j = 0; j < 16; j++) woff += (j < warp) ? wsum[j] : 0;
        const int start = woff + v - myc;
        __syncthreads();
        cnt[tid] = start;
        __syncthreads();

        for (int i = tid; i < NP; i += 512) {
            float px = sxo[i], py = syo[i], pz = szo[i];
            int slot = atomicAdd(&cnt[cell_of(px, py, pz)], 1);
            sxs[slot] = px; sys[slot] = py; szs[slot] = pz;
            sidx[slot] = (unsigned short)i;
        }
        __syncthreads();

        const int base = tid * 16;
        u64 X[8], Y[8], Z[8];
        unsigned idx2[8];
        float lox = 1e30f, loy = 1e30f, loz = 1e30f;
        float hix = -1e30f, hiy = -1e30f, hiz = -1e30f;
#pragma unroll
        for (int i = 0; i < 8; i++) {
            float x0 = sxs[base + 2 * i], x1 = sxs[base + 2 * i + 1];
            float y0 = sys[base + 2 * i], y1 = sys[base + 2 * i + 1];
            float z0 = szs[base + 2 * i], z1 = szs[base + 2 * i + 1];
            X[i] = pack2(x0, x1); Y[i] = pack2(y0, y1); Z[i] = pack2(z0, z1);
            idx2[i] = (unsigned)sidx[base + 2 * i] | ((unsigned)sidx[base + 2 * i + 1] << 16);
            lox = fminf(lox, fminf(x0, x1)); hix = fmaxf(hix, fmaxf(x0, x1));
            loy = fminf(loy, fminf(y0, y1)); hiy = fmaxf(hiy, fmaxf(y0, y1));
            loz = fminf(loz, fminf(z0, z1)); hiz = fmaxf(hiz, fmaxf(z0, z1));
        }

        float cx = sxo[0], cy = syo[0], cz = szo[0];
        float d[16];
        float tv = -1.0f;
        {
            u64 ncx = pack2(-cx, -cx), ncy = pack2(-cy, -cy), ncz = pack2(-cz, -cz);
#pragma unroll
            for (int i = 0; i < 8; i++) {
                u64 dx = add2(X[i], ncx);
                u64 dy = add2(Y[i], ncy);
                u64 dz = add2(Z[i], ncz);
                u64 nd = mul2(dx, dx);
                nd = fma2(dy, dy, nd);
                nd = fma2(dz, dz, nd);
                float n0, n1; unpack2(nd, n0, n1);
                d[2 * i + 0] = n0;
                d[2 * i + 1] = n1;
                tv = fmaxf(tv, fmaxf(n0, n1));
            }
        }
        if (tid == 0) {
            g_q[(b * MM) * 3 + 0] = cx;
            g_q[(b * MM) * 3 + 1] = cy;
            g_q[(b * MM) * 3 + 2] = cz;
        }

        for (int t = 1; t < MM; t++) {
            const unsigned tb = __float_as_uint(tv);
            unsigned wmax = redux_max(tb);
            if (lane == 0) rv[warp] = wmax;
            __syncthreads();                                  // (A)

            unsigned vmb = rv[0];
#pragma unroll
            for (int j = 1; j < 16; j++) vmb = max(vmb, rv[j]);
            const float vm = __uint_as_float(vmb);

            const int cur = t & 1;
            if (tb == vmb) {
#pragma unroll
                for (int i = 0; i < 16; i++)
                    if (d[i] == vm) {
                        int orig = (int)((idx2[i >> 1] >> ((i & 1) * 16)) & 0xFFFFu);
                        atomicMin(&s_widx[cur], orig);        // reference tie-break
                    }
            }
            if (tid == 0) s_widx[cur ^ 1] = 0x7FFFFFFF;
            __syncthreads();                                  // (B)

            const int w = s_widx[cur];
            cx = sxo[w]; cy = syo[w]; cz = szo[w];
            if (tid == 0) {
                g_q[(b * MM + t) * 3 + 0] = cx;
                g_q[(b * MM + t) * 3 + 1] = cy;
                g_q[(b * MM + t) * 3 + 2] = cz;
                if ((t & 15) == 15 || t == MM - 1) {
                    __threadfence();
                    *(volatile int*)&g_prog[b] = t + 1;
                }
            }

            float ddx = fmaxf(fmaxf(lox - cx, cx - hix), 0.0f);
            float ddy = fmaxf(fmaxf(loy - cy, cy - hiy), 0.0f);
            float ddz = fmaxf(fmaxf(loz - cz, cz - hiz), 0.0f);
            float dm2 = ddx * ddx;
            dm2 = fmaf(ddy, ddy, dm2);
            dm2 = fmaf(ddz, ddz, dm2);

            if (dm2 * 0.99999f < tv) {
                u64 ncx = pack2(-cx, -cx), ncy = pack2(-cy, -cy), ncz = pack2(-cz, -cz);
                float ntv = -1.0f;
#pragma unroll
                for (int i = 0; i < 8; i++) {
                    u64 dx = add2(X[i], ncx);
                    u64 dy = add2(Y[i], ncy);
                    u64 dz = add2(Z[i], ncz);
                    u64 nd = mul2(dx, dx);
                    nd = fma2(dy, dy, nd);
                    nd = fma2(dz, dz, nd);
                    float n0, n1; unpack2(nd, n0, n1);
                    float d0 = fminf(d[2 * i + 0], n0);
                    float d1 = fminf(d[2 * i + 1], n1);
                    d[2 * i + 0] = d0;
                    d[2 * i + 1] = d1;
                    ntv = fmaxf(ntv, fmaxf(d0, d1));
                }
                tv = ntv;
            }
        }
        return;
    }

    // ======================= worker =======================
    float* W1s  = smf;               // 67*64 = 4288
    float* b1s  = smf + 4288;        // 64
    float* W2s  = smf + 4352;        // 64*128 = 8192
    float* b2s  = smf + 12544;       // 128
    float* feat = smf + 12672;       // 64*68 = 4352
    float* h1s  = smf + 17024;       // 64*68 = 4352
    float* pmax = smf + 21376;       // 16*128 = 2048
    u64*   keys = (u64*)(smf + 23424);   // 512 * 8B

    __shared__ float qs[3];
    __shared__ int scnt2[2];

    for (int i = tid; i < FDIM * H1D; i += 512) W1s[i] = W1[i];
    for (int i = tid; i < H1D * H2D; i += 512) W2s[i] = W2[i];
    if (tid < H1D) b1s[tid] = b1[tid];
    if (tid < H2D) b2s[tid] = b2[tid];
    if (tid < 2) scnt2[tid] = 0;

    const int wb = (int)blockIdx.x - BB;
    int kk = 0;
    for (int ii = wb; ii < BB * MM; ii += NWORK, kk++) {
        const int b = ii & 3, t = ii >> 2;
        const int c = b * MM + t;

        if (tid == 0) {
            while (*(volatile int*)&g_prog[b] < t + 1) { }
            __threadfence();
            qs[0] = __ldcg(&g_q[c * 3 + 0]);
            qs[1] = __ldcg(&g_q[c * 3 + 1]);
            qs[2] = __ldcg(&g_q[c * 3 + 2]);
        }
        __syncthreads();                              // A (also orders weights/scnt init)
        const float qx = qs[0], qy = qs[1], qz = qs[2];

        const int par = kk & 1;
        int* cntp = &scnt2[par];
        const float* pb = pos + (size_t)b * NP * 3;
#pragma unroll 4
        for (int u = 0; u < 16; u++) {
            int p = tid + 512 * u;
            float px = pb[3 * p + 0], py = pb[3 * p + 1], pz = pb[3 * p + 2];
            float dx = qx - px, dy = qy - py, dz = qz - pz;
            float d2 = dx * dx + dy * dy + dz * dz;
            if (d2 <= R2C) {
                int s = atomicAdd(cntp, 1);
                if (s < CAP) keys[s] = ((u64)__float_as_uint(d2) << 32) | (unsigned)p;
            }
        }
        __syncthreads();                              // B
        const int n = min(*cntp, CAP);
        if (tid == 0) scnt2[par ^ 1] = 0;             // reset the other buffer
        if (tid >= n) keys[tid] = 0xFFFFFFFFFFFFFFFFull;
        __syncthreads();                              // C

        // bitonic sort ascending, 512 keys, one element per thread
        for (int k2 = 2; k2 <= CAP; k2 <<= 1) {
            for (int j = k2 >> 1; j > 0; j >>= 1) {
                int i1 = tid, ixj = i1 ^ j;
                if (ixj > i1) {
                    u64 a = keys[i1];
                    u64 cc = keys[ixj];
                    bool up = ((i1 & k2) == 0);
                    if ((a > cc) == up) { keys[i1] = cc; keys[ixj] = a; }
                }
                __syncthreads();
            }
        }
        const int m = min(n, KK);

        // gather features
        const float* xb = x + (size_t)b * NP * CIN;
#pragma unroll
        for (int u = 0; u < 8; u++) {
            int e = tid + 512 * u;
            int j = e >> 6, ch = e & 63;
            int row = (j < m) ? (int)(keys[j] & 0xFFFFFFFFull) : 0;
            float vv = xb[(size_t)row * CIN + ch];
            feat[j * 68 + ch] = (j < m) ? vv : 0.0f;
        }
        if (tid < KK) {
            int j = tid;
            int row = (j < m) ? (int)(keys[j] & 0xFFFFFFFFull) : 0;
            const float* pr = pb + (size_t)row * 3;
            feat[j * 68 + 64] = (j < m) ? pr[0] - qx : 0.0f;
            feat[j * 68 + 65] = (j < m) ? pr[1] - qy : 0.0f;
            feat[j * 68 + 66] = (j < m) ? pr[2] - qz : 0.0f;
            feat[j * 68 + 67] = 0.0f;
        }
        __syncthreads();                              // D

        // ---- phase 1: h1[64,64] = relu(feat @ W1 + b1), FFMA2-packed ----
        {
            const int rg = tid >> 4;                  // rows rg*2, rg*2+1
            const int cg = tid & 15;                  // cols cg*4
            float4 bv = *(const float4*)&b1s[cg * 4];
            u64 a0p = pack2(bv.x, bv.y), a0q = pack2(bv.z, bv.w);
            u64 a1p = a0p, a1q = a0q;
            const float* f0p = &feat[(rg * 2 + 0) * 68];
            const float* f1p = &feat[(rg * 2 + 1) * 68];
            for (int k = 0; k < FDIM; k++) {
                float f0 = f0p[k], f1 = f1p[k];
                float4 w = *(const float4*)&W1s[k * 64 + cg * 4];
                u64 w01 = pack2(w.x, w.y), w23 = pack2(w.z, w.w);
                u64 f0v = pack2(f0, f0), f1v = pack2(f1, f1);
                a0p = fma2(f0v, w01, a0p); a0q = fma2(f0v, w23, a0q);
                a1p = fma2(f1v, w01, a1p); a1q = fma2(f1v, w23, a1q);
            }
            float v0, v1, v2, v3;
            float4 h;
            unpack2(a0p, v0, v1); unpack2(a0q, v2, v3);
            h.x = fmaxf(v0, 0.0f); h.y = fmaxf(v1, 0.0f);
            h.z = fmaxf(v2, 0.0f); h.w = fmaxf(v3, 0.0f);
            *(float4*)&h1s[(rg * 2 + 0) * 68 + cg * 4] = h;
            unpack2(a1p, v0, v1); unpack2(a1q, v2, v3);
            h.x = fmaxf(v0, 0.0f); h.y = fmaxf(v1, 0.0f);
            h.z = fmaxf(v2, 0.0f); h.w = fmaxf(v3, 0.0f);
            *(float4*)&h1s[(rg * 2 + 1) * 68 + cg * 4] = h;
        }
        __syncthreads();                              // E

        // ---- phase 2: relu(h1 @ W2 + b2), masked max, FFMA2-packed ----
        {
            const int rg = tid >> 5;                  // rows rg*4..+3
            const int cg = tid & 31;                  // cols cg*4
            float4 bv = *(const float4*)&b2s[cg * 4];
            u64 accp[4], accq[4];
#pragma unroll
            for (int r = 0; r < 4; r++) { accp[r] = pack2(bv.x, bv.y); accq[r] = pack2(bv.z, bv.w); }
            for (int k = 0; k < H1D; k++) {
                float4 w = *(const float4*)&W2s[k * 128 + cg * 4];
                u64 w01 = pack2(w.x, w.y), w23 = pack2(w.z, w.w);
#pragma unroll
                for (int r = 0; r < 4; r++) {
                    float hv = h1s[(rg * 4 + r) * 68 + k];
                    u64 hvv = pack2(hv, hv);
                    accp[r] = fma2(hvv, w01, accp[r]);
                    accq[r] = fma2(hvv, w23, accq[r]);
                }
            }
            float mx0 = -3.402823466e38f, mx1 = mx0, mx2 = mx0, mx3 = mx0;
#pragma unroll
            for (int r = 0; r < 4; r++) {
                if (rg * 4 + r < m) {
                    float v0, v1, v2, v3;
                    unpack2(accp[r], v0, v1); unpack2(accq[r], v2, v3);
                    mx0 = fmaxf(mx0, fmaxf(v0, 0.0f));
                    mx1 = fmaxf(mx1, fmaxf(v1, 0.0f));
                    mx2 = fmaxf(mx2, fmaxf(v2, 0.0f));
                    mx3 = fmaxf(mx3, fmaxf(v3, 0.0f));
                }
            }
            float4 mv; mv.x = mx0; mv.y = mx1; mv.z = mx2; mv.w = mx3;
            *(float4*)&pmax[rg * 128 + cg * 4] = mv;
        }
        __syncthreads();                              // F

        if (tid < H2D) {
            float r = pmax[tid];
#pragma unroll
            for (int g = 1; g < 16; g++) r = fmaxf(r, pmax[g * 128 + tid]);
            if (c * H2D + tid < out_size) out[c * H2D + tid] = r;
        }
        {
            const int PO = BB * MM * H2D;
            const int BO = PO + BB * MM * 3;
            if (tid >= 128 && tid < 131) {
                int k3 = tid - 128;
                if (PO + c * 3 + k3 < out_size) out[PO + c * 3 + k3] = qs[k3];
            }
            if (tid == 131 && BO + c < out_size) out[BO + c] = (float)b;
        }
        __syncthreads();                              // G (smem reuse next iter)
    }
}

// =====================================================================
extern "C" void kernel_launch(void* const* d_in, const int* in_sizes, int n_in,
                              void* d_out, int out_size)
{
    const float* x   = (const float*)d_in[0];
    const float* pos = (const float*)d_in[1];
    const float* W1  = (const float*)d_in[3];
    const float* b1  = (const float*)d_in[4];
    const float* W2  = (const float*)d_in[5];
    const float* b2  = (const float*)d_in[6];
    float* out = (float*)d_out;

    const int FUSED_SMEM = 6 * NP * 4 + NP * 2 + 512 * 4;   // 215040 B (FPS layout is the max)
    cudaFuncSetAttribute(fused_kernel, cudaFuncAttributeMaxDynamicSharedMemorySize, FUSED_SMEM);

    reset_kernel<<<1, 32>>>();
    fused_kernel<<<BB + NWORK, 512, FUSED_SMEM>>>(x, pos, W1, b1, W2, b2, out, out_size);
}

// round 6
// speedup vs baseline: 1.9967x; 1.0213x over previous
#include <cuda_runtime.h>
#include <stdint.h>

#define NP   8192
#define MM   4096
#define BB   4
#define KK   64
#define CIN  64
#define FDIM 67
#define H1D  64
#define H2D  128
#define CAP  512
#define NWORK 144

// exact same constant the reference compares against: f32(0.2*0.2 in double)
#define R2C ((float)(0.2 * 0.2))

// -------- scratch (device globals; no allocation allowed) --------
__device__ float  g_q[BB * MM * 3];
__device__ int    g_prog[BB];
__device__ float4 g_sort[BB * NP];     // Morton-scatter staging (x,y,z,idx-bits)

// -------- packed f32x2 helpers (per-lane IEEE, bit-identical to scalar) -----
typedef unsigned long long u64;
__device__ __forceinline__ u64 pack2(float lo, float hi) {
    u64 r; asm("mov.b64 %0, {%1, %2};" : "=l"(r) : "f"(lo), "f"(hi)); return r;
}
__device__ __forceinline__ void unpack2(u64 v, float& lo, float& hi) {
    asm("mov.b64 {%0, %1}, %2;" : "=f"(lo), "=f"(hi) : "l"(v));
}
__device__ __forceinline__ u64 add2(u64 a, u64 b) {
    u64 r; asm("add.rn.f32x2 %0, %1, %2;" : "=l"(r) : "l"(a), "l"(b)); return r;
}
__device__ __forceinline__ u64 mul2(u64 a, u64 b) {
    u64 r; asm("mul.rn.f32x2 %0, %1, %2;" : "=l"(r) : "l"(a), "l"(b)); return r;
}
__device__ __forceinline__ u64 fma2(u64 a, u64 b, u64 c) {
    u64 r; asm("fma.rn.f32x2 %0, %1, %2, %3;" : "=l"(r) : "l"(a), "l"(b), "l"(c)); return r;
}
__device__ __forceinline__ unsigned redux_max(unsigned v) {
    unsigned r; asm("redux.sync.max.u32 %0, %1, 0xffffffff;" : "=r"(r) : "r"(v)); return r;
}
__device__ __forceinline__ u64 shfl_xor64(u64 v, int m) {
    unsigned lo = (unsigned)v, hi = (unsigned)(v >> 32);
    lo = __shfl_xor_sync(0xffffffffu, lo, m);
    hi = __shfl_xor_sync(0xffffffffu, hi, m);
    return ((u64)hi << 32) | (u64)lo;
}
__device__ __forceinline__ int spread3(int v) {
    return (v & 1) | ((v & 2) << 2) | ((v & 4) << 4);
}
__device__ __forceinline__ int cell_of(float px, float py, float pz) {
    int cx = min(7, max(0, (int)(px * 8.0f)));
    int cy = min(7, max(0, (int)(py * 8.0f)));
    int cz = min(7, max(0, (int)(pz * 8.0f)));
    return spread3(cx) | (spread3(cy) << 1) | (spread3(cz) << 2);
}

__global__ void reset_kernel() {
    if (threadIdx.x < BB) g_prog[threadIdx.x] = 0;
}

// =====================================================================
// Fused persistent kernel (100KB dynamic smem -> 128KB L1 stays live).
// Blocks 0..3: FPS producer (one per cloud), publishing g_prog every 16.
// Blocks 4..147: workers — per centroid: spin-wait, radius scan (L1-hot
// pos), register/shfl bitonic top-K, float4 gather, FFMA2 MLP, masked max.
// =====================================================================
__global__ void __launch_bounds__(512, 1) fused_kernel(
    const float* __restrict__ x, const float* __restrict__ pos,
    const float* __restrict__ W1, const float* __restrict__ b1,
    const float* __restrict__ W2, const float* __restrict__ b2,
    float* __restrict__ out, int out_size)
{
    extern __shared__ float smf[];
    const int tid = threadIdx.x;

    if (blockIdx.x < BB) {
        // ======================= FPS producer =======================
        float* sxo = smf;                 // [NP] original order
        float* syo = smf + NP;
        float* szo = smf + 2 * NP;
        int* cnt = (int*)(smf + 3 * NP);  // [512]

        __shared__ unsigned rv[16];
        __shared__ int wsum[16];
        __shared__ int s_widx[2];

        const int b = blockIdx.x;
        const int lane = tid & 31, warp = tid >> 5;
        const float* pb = pos + (size_t)b * NP * 3;

        cnt[tid] = 0;
        if (tid == 0) { s_widx[0] = 0x7FFFFFFF; s_widx[1] = 0x7FFFFFFF; }
        __syncthreads();
        for (int i = tid; i < NP; i += 512) {
            float px = pb[3 * i + 0], py = pb[3 * i + 1], pz = pb[3 * i + 2];
            sxo[i] = px; syo[i] = py; szo[i] = pz;
            atomicAdd(&cnt[cell_of(px, py, pz)], 1);
        }
        __syncthreads();

        int myc = cnt[tid];
        int v = myc;
#pragma unroll
        for (int o = 1; o < 32; o <<= 1) {
            int n = __shfl_up_sync(0xffffffffu, v, o);
            if (lane >= o) v += n;
        }
        if (lane == 31) wsum[warp] = v;
        __syncthreads();
        int woff = 0;
#pragma unroll
        for (int j = 0; j < 16; j++) woff += (j < warp) ? wsum[j] : 0;
        const int start = woff + v - myc;
        __syncthreads();
        cnt[tid] = start;
        __syncthreads();

        // scatter into Morton order -> GLOBAL scratch (one-time)
        for (int i = tid; i < NP; i += 512) {
            float px = sxo[i], py = syo[i], pz = szo[i];
            int slot = atomicAdd(&cnt[cell_of(px, py, pz)], 1);
            float4 rec; rec.x = px; rec.y = py; rec.z = pz; rec.w = __int_as_float(i);
            g_sort[b * NP + slot] = rec;
        }
        __syncthreads();   // global writes visible block-wide after bar

        const int base = tid * 16;
        u64 X[8], Y[8], Z[8];
        unsigned idx2[8];
        float lox = 1e30f, loy = 1e30f, loz = 1e30f;
        float hix = -1e30f, hiy = -1e30f, hiz = -1e30f;
#pragma unroll
        for (int i = 0; i < 8; i++) {
            float4 v0 = g_sort[b * NP + base + 2 * i];
            float4 v1 = g_sort[b * NP + base + 2 * i + 1];
            X[i] = pack2(v0.x, v1.x); Y[i] = pack2(v0.y, v1.y); Z[i] = pack2(v0.z, v1.z);
            idx2[i] = (__float_as_uint(v0.w) & 0xFFFFu) | (__float_as_uint(v1.w) << 16);
            lox = fminf(lox, fminf(v0.x, v1.x)); hix = fmaxf(hix, fmaxf(v0.x, v1.x));
            loy = fminf(loy, fminf(v0.y, v1.y)); hiy = fmaxf(hiy, fmaxf(v0.y, v1.y));
            loz = fminf(loz, fminf(v0.z, v1.z)); hiz = fmaxf(hiz, fmaxf(v0.z, v1.z));
        }

        float cx = sxo[0], cy = syo[0], cz = szo[0];
        float d[16];
        float tv = -1.0f;
        {
            u64 ncx = pack2(-cx, -cx), ncy = pack2(-cy, -cy), ncz = pack2(-cz, -cz);
#pragma unroll
            for (int i = 0; i < 8; i++) {
                u64 dx = add2(X[i], ncx);
                u64 dy = add2(Y[i], ncy);
                u64 dz = add2(Z[i], ncz);
                u64 nd = mul2(dx, dx);
                nd = fma2(dy, dy, nd);
                nd = fma2(dz, dz, nd);
                float n0, n1; unpack2(nd, n0, n1);
                d[2 * i + 0] = n0;
                d[2 * i + 1] = n1;
                tv = fmaxf(tv, fmaxf(n0, n1));
            }
        }
        if (tid == 0) {
            g_q[(b * MM) * 3 + 0] = cx;
            g_q[(b * MM) * 3 + 1] = cy;
            g_q[(b * MM) * 3 + 2] = cz;
        }

        for (int t = 1; t < MM; t++) {
            const unsigned tb = __float_as_uint(tv);
            unsigned wmax = redux_max(tb);
            if (lane == 0) rv[warp] = wmax;
            __syncthreads();                                  // (A)

            unsigned vmb = rv[0];
#pragma unroll
            for (int j = 1; j < 16; j++) vmb = max(vmb, rv[j]);
            const float vm = __uint_as_float(vmb);

            const int cur = t & 1;
            if (tb == vmb) {
#pragma unroll
                for (int i = 0; i < 16; i++)
                    if (d[i] == vm) {
                        int orig = (int)((idx2[i >> 1] >> ((i & 1) * 16)) & 0xFFFFu);
                        atomicMin(&s_widx[cur], orig);        // reference tie-break
                    }
            }
            if (tid == 0) s_widx[cur ^ 1] = 0x7FFFFFFF;
            __syncthreads();                                  // (B)

            const int w = s_widx[cur];
            cx = sxo[w]; cy = syo[w]; cz = szo[w];
            if (tid == 0) {
                g_q[(b * MM + t) * 3 + 0] = cx;
                g_q[(b * MM + t) * 3 + 1] = cy;
                g_q[(b * MM + t) * 3 + 2] = cz;
                if ((t & 15) == 15 || t == MM - 1) {
                    __threadfence();
                    *(volatile int*)&g_prog[b] = t + 1;
                }
            }

            float ddx = fmaxf(fmaxf(lox - cx, cx - hix), 0.0f);
            float ddy = fmaxf(fmaxf(loy - cy, cy - hiy), 0.0f);
            float ddz = fmaxf(fmaxf(loz - cz, cz - hiz), 0.0f);
            float dm2 = ddx * ddx;
            dm2 = fmaf(ddy, ddy, dm2);
            dm2 = fmaf(ddz, ddz, dm2);

            if (dm2 * 0.99999f < tv) {
                u64 ncx = pack2(-cx, -cx), ncy = pack2(-cy, -cy), ncz = pack2(-cz, -cz);
                float ntv = -1.0f;
#pragma unroll
                for (int i = 0; i < 8; i++) {
                    u64 dx = add2(X[i], ncx);
                    u64 dy = add2(Y[i], ncy);
                    u64 dz = add2(Z[i], ncz);
                    u64 nd = mul2(dx, dx);
                    nd = fma2(dy, dy, nd);
                    nd = fma2(dz, dz, nd);
                    float n0, n1; unpack2(nd, n0, n1);
                    float d0 = fminf(d[2 * i + 0], n0);
                    float d1 = fminf(d[2 * i + 1], n1);
                    d[2 * i + 0] = d0;
                    d[2 * i + 1] = d1;
                    ntv = fmaxf(ntv, fmaxf(d0, d1));
                }
                tv = ntv;
            }
        }
        return;
    }

    // ======================= worker =======================
    float* W1s  = smf;               // 67*64 = 4288
    float* b1s  = smf + 4288;        // 64
    float* W2s  = smf + 4352;        // 64*128 = 8192
    float* b2s  = smf + 12544;       // 128
    float* feat = smf + 12672;       // 64*68 = 4352
    float* h1s  = smf + 17024;       // 64*68 = 4352
    float* pmax = smf + 21376;       // 16*128 = 2048
    u64*   keys = (u64*)(smf + 23424);   // 512 * 8B -> ends 97792B

    __shared__ float qs[3];
    __shared__ int scnt2[2];

    for (int i = tid; i < FDIM * H1D; i += 512) W1s[i] = W1[i];
    for (int i = tid; i < H1D * H2D; i += 512) W2s[i] = W2[i];
    if (tid < H1D) b1s[tid] = b1[tid];
    if (tid < H2D) b2s[tid] = b2[tid];
    if (tid < 2) scnt2[tid] = 0;

    const int wb = (int)blockIdx.x - BB;
    const int b = wb & 3;                        // fixed cloud per block (144 % 4 == 0)
    const float* pb = pos + (size_t)b * NP * 3;
    const float4* xb4 = (const float4*)(x + (size_t)b * NP * CIN);
    int kk = 0;
    for (int ii = wb; ii < BB * MM; ii += NWORK, kk++) {
        const int t = ii >> 2;
        const int c = b * MM + t;

        if (tid == 0) {
            while (*(volatile int*)&g_prog[b] < t + 1) { }
            __threadfence();
            qs[0] = __ldcg(&g_q[c * 3 + 0]);
            qs[1] = __ldcg(&g_q[c * 3 + 1]);
            qs[2] = __ldcg(&g_q[c * 3 + 2]);
        }
        __syncthreads();                              // A
        const float qx = qs[0], qy = qs[1], qz = qs[2];

        const int par = kk & 1;
        int* cntp = &scnt2[par];
#pragma unroll 4
        for (int u = 0; u < 16; u++) {
            int p = tid + 512 * u;
            float px = pb[3 * p + 0], py = pb[3 * p + 1], pz = pb[3 * p + 2];
            float dx = qx - px, dy = qy - py, dz = qz - pz;
            float d2 = dx * dx + dy * dy + dz * dz;
            if (d2 <= R2C) {
                int s = atomicAdd(cntp, 1);
                if (s < CAP) keys[s] = ((u64)__float_as_uint(d2) << 32) | (unsigned)p;
            }
        }
        __syncthreads();                              // B
        const int n = min(*cntp, CAP);
        if (tid == 0) scnt2[par ^ 1] = 0;             // reset other buffer

        // -------- register/shfl bitonic sort, 512 keys ascending --------
        u64 key = (tid < n) ? keys[tid] : 0xFFFFFFFFFFFFFFFFull;
#pragma unroll
        for (int k2 = 2; k2 <= CAP; k2 <<= 1) {
#pragma unroll
            for (int j = k2 >> 1; j > 0; j >>= 1) {
                const bool asc = ((tid & k2) == 0);
                u64 other;
                if (j >= 32) {
                    __syncthreads();
                    keys[tid] = key;
                    __syncthreads();
                    other = keys[tid ^ j];
                } else {
                    other = shfl_xor64(key, j);
                }
                const bool lower = ((tid & j) == 0);
                const bool keepMin = (lower == asc);
                const bool less = key < other;
                key = (less == keepMin) ? key : other;
            }
        }
        __syncthreads();
        keys[tid] = key;
        __syncthreads();                              // C
        const int m = min(n, KK);

        // -------- gather features (float4) --------
#pragma unroll
        for (int u = 0; u < 2; u++) {
            int q = tid + 512 * u;                    // 0..1023
            int j = q >> 4, c4 = q & 15;
            int row = (j < m) ? (int)(keys[j] & 0xFFFFFFFFull) : 0;
            float4 vv = xb4[(size_t)row * 16 + c4];
            if (j >= m) { vv.x = 0.0f; vv.y = 0.0f; vv.z = 0.0f; vv.w = 0.0f; }
            *(float4*)&feat[j * 68 + c4 * 4] = vv;
        }
        if (tid < KK) {
            int j = tid;
            int row = (j < m) ? (int)(keys[j] & 0xFFFFFFFFull) : 0;
            const float* pr = pb + (size_t)row * 3;
            feat[j * 68 + 64] = (j < m) ? pr[0] - qx : 0.0f;
            feat[j * 68 + 65] = (j < m) ? pr[1] - qy : 0.0f;
            feat[j * 68 + 66] = (j < m) ? pr[2] - qz : 0.0f;
            feat[j * 68 + 67] = 0.0f;
        }
        __syncthreads();                              // D

        // ---- phase 1: h1[64,64] = relu(feat @ W1 + b1), FFMA2-packed ----
        {
            const int rg = tid >> 4;                  // rows rg*2, rg*2+1
            const int cg = tid & 15;                  // cols cg*4
            float4 bv = *(const float4*)&b1s[cg * 4];
            u64 a0p = pack2(bv.x, bv.y), a0q = pack2(bv.z, bv.w);
            u64 a1p = a0p, a1q = a0q;
            const float* f0p = &feat[(rg * 2 + 0) * 68];
            const float* f1p = &feat[(rg * 2 + 1) * 68];
            for (int k = 0; k < FDIM; k++) {
                float f0 = f0p[k], f1 = f1p[k];
                float4 w = *(const float4*)&W1s[k * 64 + cg * 4];
                u64 w01 = pack2(w.x, w.y), w23 = pack2(w.z, w.w);
                u64 f0v = pack2(f0, f0), f1v = pack2(f1, f1);
                a0p = fma2(f0v, w01, a0p); a0q = fma2(f0v, w23, a0q);
                a1p = fma2(f1v, w01, a1p); a1q = fma2(f1v, w23, a1q);
            }
            float v0, v1, v2, v3;
            float4 h;
            unpack2(a0p, v0, v1); unpack2(a0q, v2, v3);
            h.x = fmaxf(v0, 0.0f); h.y = fmaxf(v1, 0.0f);
            h.z = fmaxf(v2, 0.0f); h.w = fmaxf(v3, 0.0f);
            *(float4*)&h1s[(rg * 2 + 0) * 68 + cg * 4] = h;
            unpack2(a1p, v0, v1); unpack2(a1q, v2, v3);
            h.x = fmaxf(v0, 0.0f); h.y = fmaxf(v1, 0.0f);
            h.z = fmaxf(v2, 0.0f); h.w = fmaxf(v3, 0.0f);
            *(float4*)&h1s[(rg * 2 + 1) * 68 + cg * 4] = h;
        }
        __syncthreads();                              // E

        // ---- phase 2: relu(h1 @ W2 + b2), masked max, FFMA2-packed ----
        {
            const int rg = tid >> 5;                  // rows rg*4..+3
            const int cg = tid & 31;                  // cols cg*4
            float4 bv = *(const float4*)&b2s[cg * 4];
            u64 accp[4], accq[4];
#pragma unroll
            for (int r = 0; r < 4; r++) { accp[r] = pack2(bv.x, bv.y); accq[r] = pack2(bv.z, bv.w); }
            for (int k = 0; k < H1D; k++) {
                float4 w = *(const float4*)&W2s[k * 128 + cg * 4];
                u64 w01 = pack2(w.x, w.y), w23 = pack2(w.z, w.w);
#pragma unroll
                for (int r = 0; r < 4; r++) {
                    float hv = h1s[(rg * 4 + r) * 68 + k];
                    u64 hvv = pack2(hv, hv);
                    accp[r] = fma2(hvv, w01, accp[r]);
                    accq[r] = fma2(hvv, w23, accq[r]);
                }
            }
            float mx0 = -3.402823466e38f, mx1 = mx0, mx2 = mx0, mx3 = mx0;
#pragma unroll
            for (int r = 0; r < 4; r++) {
                if (rg * 4 + r < m) {
                    float v0, v1, v2, v3;
                    unpack2(accp[r], v0, v1); unpack2(accq[r], v2, v3);
                    mx0 = fmaxf(mx0, fmaxf(v0, 0.0f));
                    mx1 = fmaxf(mx1, fmaxf(v1, 0.0f));
                    mx2 = fmaxf(mx2, fmaxf(v2, 0.0f));
                    mx3 = fmaxf(mx3, fmaxf(v3, 0.0f));
                }
            }
            float4 mv; mv.x = mx0; mv.y = mx1; mv.z = mx2; mv.w = mx3;
            *(float4*)&pmax[rg * 128 + cg * 4] = mv;
        }
        __syncthreads();                              // F

        if (tid < H2D) {
            float r = pmax[tid];
#pragma unroll
            for (int g = 1; g < 16; g++) r = fmaxf(r, pmax[g * 128 + tid]);
            if (c * H2D + tid < out_size) out[c * H2D + tid] = r;
        }
        {
            const int PO = BB * MM * H2D;
            const int BO = PO + BB * MM * 3;
            if (tid >= 128 && tid < 131) {
                int k3 = tid - 128;
                if (PO + c * 3 + k3 < out_size) out[PO + c * 3 + k3] = qs[k3];
            }
            if (tid == 131 && BO + c < out_size) out[BO + c] = (float)b;
        }
        __syncthreads();                              // G (smem reuse next iter)
    }
}

// =====================================================================
extern "C" void kernel_launch(void* const* d_in, const int* in_sizes, int n_in,
                              void* d_out, int out_size)
{
    const float* x   = (const float*)d_in[0];
    const float* pos = (const float*)d_in[1];
    const float* W1  = (const float*)d_in[3];
    const float* b1  = (const float*)d_in[4];
    const float* W2  = (const float*)d_in[5];
    const float* b2  = (const float*)d_in[6];
    float* out = (float*)d_out;

    const int FUSED_SMEM = 3 * NP * 4 + 512 * 4;   // 100352 B (FPS layout is the max)
    cudaFuncSetAttribute(fused_kernel, cudaFuncAttributeMaxDynamicSharedMemorySize, FUSED_SMEM);

    reset_kernel<<<1, 32>>>();
    fused_kernel<<<BB + NWORK, 512, FUSED_SMEM>>>(x, pos, W1, b1, W2, b2, out, out_size);
}